// round 12
// baseline (speedup 1.0000x reference)
#include <cuda_runtime.h>
#include <stdint.h>

#define NB 32
#define CI 32
#define CO 32
#define HH 128
#define WW 128
#define GRID 256

// Scratch (static __device__ arrays: allocation-free, graph-safe)
__device__ signed char g_act_nhwc[(size_t)NB * HH * WW * CI];  // 16 MB NHWC int8
__device__ int g_max;
__device__ unsigned g_wpack[CO * 9 * 8];   // packed weights
__device__ unsigned g_c1, g_c2, g_c3;      // grid-barrier counters (self-reset)

__device__ __forceinline__ void mma_s8(int d[4], const unsigned a[4],
                                       unsigned b0, unsigned b1) {
    asm volatile(
        "mma.sync.aligned.m16n8k32.row.col.s32.s8.s8.s32 "
        "{%0,%1,%2,%3}, {%4,%5,%6,%7}, {%8,%9}, {%0,%1,%2,%3};\n"
        : "+r"(d[0]), "+r"(d[1]), "+r"(d[2]), "+r"(d[3])
        : "r"(a[0]), "r"(a[1]), "r"(a[2]), "r"(a[3]), "r"(b0), "r"(b1));
}

__device__ __forceinline__ void ldm4(unsigned r[4], unsigned saddr) {
    asm volatile(
        "ldmatrix.sync.aligned.m8n8.x4.shared.b16 {%0,%1,%2,%3}, [%4];\n"
        : "=r"(r[0]), "=r"(r[1]), "=r"(r[2]), "=r"(r[3])
        : "r"(saddr));
}

// swizzle: XOR bit4 with bit7 of the byte offset
__device__ __forceinline__ unsigned swz(unsigned off) {
    return off ^ ((off >> 3) & 16);
}

// Bit-exact replica of psto_shift + act_calc select paths.
__device__ __forceinline__ float quantize_one(int v, int shift, int eff) {
    if (shift < 1) return (float)(signed char)v;  // truncating int8 cast
    int rt = v >> eff;                            // floor division by 2^eff
    int prob = v & ((1 << eff) - 1);              // non-negative remainder
    int h = eff >> 1;
    int qp = prob >> h;
    int pr = prob & ((1 << h) - 1);
    if (eff & 1) pr <<= 1;
    int sgn = (v >> 31) | 1;                      // v==0 never decrements (prob=0)
    int r = rt + ((qp <= pr) ? 0 : sgn);
    r = r < -127 ? -127 : (r > 127 ? 127 : r);
    return (float)r;
}

// Grid barrier: producer-fence -> arrive -> spin -> consumer-fence.
// All GRID blocks are simultaneously resident (GRID=256 <= 148 SMs * 2).
__device__ __forceinline__ void gbar(unsigned* c) {
    __syncthreads();
    if (threadIdx.x == 0) {
        __threadfence();
        atomicAdd(c, 1u);
        while (atomicAdd(c, 0u) < GRID) {
        }
        __threadfence();
    }
    __syncthreads();
}

// One conv pass over this block's 4 tiles (tile = bl + k*256).
// Tile = 4 output rows of one image. 8 warps: warp w -> rows (w>>2)*2..+1,
// x-segment (w&3)*32. MODE 0: return local |max|. MODE 1: quantize + store.
template <int MODE>
__device__ __forceinline__ int conv_pass(signed char* s_act, signed char* s_w,
                                         int bl, int shift, int eff,
                                         float* __restrict__ out) {
    int tid = threadIdx.x;
    int lane = tid & 31;
    int wid = tid >> 5;
    int r0 = (wid >> 2) << 1;
    int xbase = (wid & 3) << 5;

    unsigned actS = (unsigned)__cvta_generic_to_shared(s_act);
    unsigned wS = (unsigned)__cvta_generic_to_shared(s_w);
    unsigned alane = ((unsigned)(lane & 15) << 5) + ((lane >> 4) << 4);
    unsigned bbase = ((unsigned)(((lane >> 4) << 3) + (lane & 7)) << 5) +
                     (((lane >> 3) & 1) << 4);
    int g = lane >> 2;
    int tig = lane & 3;
    int mret = 0;

#pragma unroll 1
    for (int kt = 0; kt < 4; kt++) {
        int tile = bl + (kt << 8);
        int n = tile >> 5;
        int y0 = (tile & 31) << 2;

        __syncthreads();  // previous tile fully consumed
        uint4* sa4 = (uint4*)s_act;
#pragma unroll
        for (int i = tid; i < 6 * 130 * 32 / 16; i += 256)
            sa4[i] = make_uint4(0, 0, 0, 0);
        __syncthreads();
        {
            int px = tid >> 1;
            int half = (tid & 1) << 4;
#pragma unroll
            for (int r = 0; r < 6; r++) {
                int iy = y0 + r - 1;
                if ((unsigned)iy < HH) {
                    const uint4* src = (const uint4*)(g_act_nhwc +
                        ((((size_t)n * HH + iy) * WW + px) << 5) + half);
                    unsigned off = ((unsigned)((r * 130 + px + 1) << 5)) + half;
                    *(uint4*)(s_act + swz(off)) = *src;
                }
            }
        }
        __syncthreads();

        int acc[2][2][4][4];
#pragma unroll
        for (int rr = 0; rr < 2; rr++)
#pragma unroll
            for (int m = 0; m < 2; m++)
#pragma unroll
                for (int ns = 0; ns < 4; ns++)
#pragma unroll
                    for (int k = 0; k < 4; k++) acc[rr][m][ns][k] = 0;

#pragma unroll
        for (int kx = 0; kx < 3; kx++) {
            unsigned bf[3][2][4];
#pragma unroll
            for (int ky = 0; ky < 3; ky++) {
                unsigned bo = bbase + ((unsigned)(ky * 3 + kx) << 10);
                ldm4(bf[ky][0], wS + swz(bo));
                ldm4(bf[ky][1], wS + swz(bo + 512));
            }
#pragma unroll
            for (int ra = 0; ra < 4; ra++) {
                unsigned af[2][4];
                unsigned ao = alane +
                    ((unsigned)((r0 + ra) * 130 + xbase + kx) << 5);
                ldm4(af[0], actS + swz(ao));
                ldm4(af[1], actS + swz(ao + 512));
#pragma unroll
                for (int rr = 0; rr < 2; rr++) {
                    int ky = ra - rr;
                    if (ky >= 0 && ky < 3) {
#pragma unroll
                        for (int m = 0; m < 2; m++) {
                            mma_s8(acc[rr][m][0], af[m], bf[ky][0][0], bf[ky][0][1]);
                            mma_s8(acc[rr][m][1], af[m], bf[ky][0][2], bf[ky][0][3]);
                            mma_s8(acc[rr][m][2], af[m], bf[ky][1][0], bf[ky][1][1]);
                            mma_s8(acc[rr][m][3], af[m], bf[ky][1][2], bf[ky][1][3]);
                        }
                    }
                }
            }
        }

        if (MODE == 0) {
#pragma unroll
            for (int rr = 0; rr < 2; rr++)
#pragma unroll
                for (int m = 0; m < 2; m++)
#pragma unroll
                    for (int ns = 0; ns < 4; ns++)
#pragma unroll
                        for (int k = 0; k < 4; k++) {
                            int a = acc[rr][m][ns][k];
                            mret = max(mret, a < 0 ? -a : a);
                        }
        } else {
#pragma unroll
            for (int rr = 0; rr < 2; rr++) {
                int y = y0 + r0 + rr;
#pragma unroll
                for (int m = 0; m < 2; m++)
#pragma unroll
                    for (int ns = 0; ns < 4; ns++) {
                        int x0p = xbase + m * 16 + g;
                        int co0 = ns * 8 + tig * 2;
                        float* base0 = out + (((n * 32 + co0) * 128 + y) * 128);
                        float* base1 = base0 + 128 * 128;
                        base0[x0p] = quantize_one(acc[rr][m][ns][0], shift, eff);
                        base1[x0p] = quantize_one(acc[rr][m][ns][1], shift, eff);
                        base0[x0p + 8] = quantize_one(acc[rr][m][ns][2], shift, eff);
                        base1[x0p + 8] = quantize_one(acc[rr][m][ns][3], shift, eff);
                    }
            }
        }
    }
    return mret;
}

__global__ void __launch_bounds__(256, 2) k_fused(
    const int* __restrict__ act, const int* __restrict__ expin,
    const int* __restrict__ w, const int* __restrict__ wexp,
    float* __restrict__ out, int out_size) {
    __shared__ __align__(128) signed char s_act[6 * 130 * 32];
    __shared__ __align__(128) signed char s_w[9 * 32 * 32];

    int tid = threadIdx.x;
    int bl = blockIdx.x;

    // ---- Phase 1: NCHW int32 -> NHWC int8 (16 chunks per block) ----
#pragma unroll 1
    for (int it = 0; it < 16; it++) {
        int idx = (bl * 16 + it) * 256 + tid;
        int half = idx & 1;
        int p = idx >> 1;
        int x = p & (WW - 1);
        int y = (p >> 7) & (HH - 1);
        int n = p >> 14;
        const int* src = act + ((size_t)(n * CI + half * 16) * HH + y) * WW + x;
        unsigned vv[4];
#pragma unroll
        for (int j = 0; j < 4; j++) {
            unsigned v = 0;
#pragma unroll
            for (int bb = 0; bb < 4; bb++) {
                unsigned c = (unsigned)src[(size_t)(j * 4 + bb) * HH * WW] & 0xFFu;
                v |= c << (8 * bb);
            }
            vv[j] = v;
        }
        *(uint4*)(g_act_nhwc + ((size_t)p << 5) + (half << 4)) =
            make_uint4(vv[0], vv[1], vv[2], vv[3]);
    }
    // block 0: pack weights + reset g_max (read in later phases only)
    if (bl == 0) {
        if (tid == 0) g_max = 0;
        for (int i = tid; i < CO * 9 * 8; i += 256) {
            int ciw = i & 7;
            int t = (i >> 3) % 9;
            int co = i / 72;
            int kh = t / 3, kw = t - kh * 3;
            unsigned v = 0;
#pragma unroll
            for (int j = 0; j < 4; j++) {
                int ci = ciw * 4 + j;
                unsigned b = (unsigned)(w[((co * CI + ci) * 3 + kh) * 3 + kw]) & 0xFFu;
                v |= b << (8 * j);
            }
            g_wpack[i] = v;
        }
    }
    gbar(&g_c1);

    // fill s_w (swizzled); first __syncthreads inside conv_pass publishes it
    for (int i = tid; i < 9 * 32 * 2; i += 256) {
        int h = i & 1;
        int co = (i >> 1) & 31;
        int t = i >> 6;
        unsigned off = ((unsigned)(t * 32 + co) << 5) + (h << 4);
        *(uint4*)(s_w + swz(off)) = ((const uint4*)g_wpack)[(co * 9 + t) * 2 + h];
    }

    // ---- Phase 2: conv, global |max| ----
    int mloc = conv_pass<0>(s_act, s_w, bl, 0, 0, out);
    mloc = __reduce_max_sync(0xffffffffu, mloc);
    if ((tid & 31) == 0) atomicMax(&g_max, mloc);
    gbar(&g_c2);

    // ---- Phase 3: recompute conv, quantize, store ----
    int gmax = *(volatile int*)&g_max;
    int bw = gmax ? (32 - __clz(gmax - 1)) : 0;  // exact ceil(log2)
    int shift = bw - 7;
    int eff = shift > 1 ? shift : 2;
    conv_pass<1>(s_act, s_w, bl, shift, eff, out);

    if (bl == 0 && tid == 0) {
        int inc = shift > 1 ? shift : (shift == 1 ? 2 : 0);
        int e = expin[0] + wexp[0] + inc;
        out[out_size - 1] = (float)(signed char)e;
    }

    // ---- Final: last block to finish resets barrier counters for next launch
    __syncthreads();
    if (tid == 0) {
        __threadfence();
        unsigned old = atomicAdd(&g_c3, 1u);
        if (old == GRID - 1) {
            atomicExch(&g_c1, 0u);
            atomicExch(&g_c2, 0u);
            atomicExch(&g_c3, 0u);
        }
    }
}

extern "C" void kernel_launch(void* const* d_in, const int* in_sizes, int n_in,
                              void* d_out, int out_size) {
    const int* act = (const int*)d_in[0];
    const int* expin = (const int*)d_in[1];
    const int* w = (const int*)d_in[2];
    const int* wexp = (const int*)d_in[3];
    float* out = (float*)d_out;

    k_fused<<<GRID, 256>>>(act, expin, w, wexp, out, out_size);
}

// round 13
// speedup vs baseline: 1.1072x; 1.1072x over previous
#include <cuda_runtime.h>
#include <stdint.h>

#define NB 32
#define CI 32
#define CO 32
#define HH 128
#define WW 128
#define GRID 296          // 148 SMs x 2 resident blocks (guaranteed by launch bounds)
#define NTILE 2048        // 2-row tiles: 32 images x 64

// Scratch (static __device__ arrays: allocation-free, graph-safe)
__device__ signed char g_act_nhwc[(size_t)NB * HH * WW * CI];  // 16 MB NHWC int8
__device__ int g_max;
__device__ unsigned g_wpack[CO * 9 * 8];   // packed weights
__device__ unsigned g_c1, g_c2, g_c3;      // grid-barrier counters (self-reset)

__device__ __forceinline__ void mma_s8(int d[4], const unsigned a[4],
                                       unsigned b0, unsigned b1) {
    asm volatile(
        "mma.sync.aligned.m16n8k32.row.col.s32.s8.s8.s32 "
        "{%0,%1,%2,%3}, {%4,%5,%6,%7}, {%8,%9}, {%0,%1,%2,%3};\n"
        : "+r"(d[0]), "+r"(d[1]), "+r"(d[2]), "+r"(d[3])
        : "r"(a[0]), "r"(a[1]), "r"(a[2]), "r"(a[3]), "r"(b0), "r"(b1));
}

__device__ __forceinline__ void ldm4(unsigned r[4], unsigned saddr) {
    asm volatile(
        "ldmatrix.sync.aligned.m8n8.x4.shared.b16 {%0,%1,%2,%3}, [%4];\n"
        : "=r"(r[0]), "=r"(r[1]), "=r"(r[2]), "=r"(r[3])
        : "r"(saddr));
}

// swizzle: XOR bit4 with bit7 of the byte offset
__device__ __forceinline__ unsigned swz(unsigned off) {
    return off ^ ((off >> 3) & 16);
}

// Bit-exact replica of psto_shift + act_calc select paths.
__device__ __forceinline__ float quantize_one(int v, int shift, int eff) {
    if (shift < 1) return (float)(signed char)v;  // truncating int8 cast
    int rt = v >> eff;                            // floor division by 2^eff
    int prob = v & ((1 << eff) - 1);              // non-negative remainder
    int h = eff >> 1;
    int qp = prob >> h;
    int pr = prob & ((1 << h) - 1);
    if (eff & 1) pr <<= 1;
    int sgn = (v >> 31) | 1;                      // v==0 never decrements (prob=0)
    int r = rt + ((qp <= pr) ? 0 : sgn);
    r = r < -127 ? -127 : (r > 127 ? 127 : r);
    return (float)r;
}

// Grid barrier: producer-fence -> arrive -> spin -> consumer-fence.
__device__ __forceinline__ void gbar(unsigned* c) {
    __syncthreads();
    if (threadIdx.x == 0) {
        __threadfence();
        atomicAdd(c, 1u);
        while (atomicAdd(c, 0u) < GRID) {
        }
        __threadfence();
    }
    __syncthreads();
}

// Conv over this block's tiles (tile = bl, bl+GRID, ...). Tile = 2 output rows.
// 8 warps: warp w -> row (w>>2), x-seg (w&3)*32. Warp tile = 32 px x 32 co.
// MODE 0: return local |max|. MODE 1: quantize + float store.
template <int MODE>
__device__ __forceinline__ int conv_pass(signed char* s_act, signed char* s_w,
                                         int shift, int eff,
                                         float* __restrict__ out) {
    int tid = threadIdx.x;
    int lane = tid & 31;
    int wid = tid >> 5;
    int row = wid >> 2;
    int xbase = (wid & 3) << 5;

    unsigned actS = (unsigned)__cvta_generic_to_shared(s_act);
    unsigned wS = (unsigned)__cvta_generic_to_shared(s_w);
    unsigned abase = ((unsigned)(row * 130 + xbase + (lane & 15)) << 5) +
                     ((lane >> 4) << 4);
    unsigned bbase = ((unsigned)(((lane >> 4) << 3) + (lane & 7)) << 5) +
                     (((lane >> 3) & 1) << 4);
    int g = lane >> 2;
    int tig = lane & 3;
    int mret = 0;

#pragma unroll 1
    for (int tile = blockIdx.x; tile < NTILE; tile += GRID) {
        int n = tile >> 6;
        int y0 = (tile & 63) << 1;

        __syncthreads();  // previous tile fully consumed / s_w published
        // zero x-halo columns (cols 0 and 129, 4 rows, both 16B halves)
        if (tid < 16) {
            int r = tid & 3;
            int col = ((tid >> 2) & 1) ? 129 : 0;
            unsigned half = (unsigned)(tid >> 3) << 4;
            unsigned off = ((unsigned)(r * 130 + col) << 5) + half;
            *(uint4*)(s_act + swz(off)) = make_uint4(0, 0, 0, 0);
        }
        // zero y-boundary rows (benign overlap with halo-col zeros: same value)
        if (y0 == 0)
            for (int i = tid; i < 260; i += 256)
                ((uint4*)s_act)[i] = make_uint4(0, 0, 0, 0);
        if (y0 == 126)
            for (int i = tid; i < 260; i += 256)
                ((uint4*)s_act)[780 + i] = make_uint4(0, 0, 0, 0);
        // fill interior: 4 rows x 128 px x 32B, swizzled
        {
            int px = tid >> 1;
            int half = (tid & 1) << 4;
#pragma unroll
            for (int r = 0; r < 4; r++) {
                int iy = y0 + r - 1;
                if ((unsigned)iy < HH) {
                    const uint4* src = (const uint4*)(g_act_nhwc +
                        ((((size_t)n * HH + iy) * WW + px) << 5) + half);
                    unsigned off = ((unsigned)((r * 130 + px + 1) << 5)) + half;
                    *(uint4*)(s_act + swz(off)) = *src;
                }
            }
        }
        __syncthreads();

        int acc[2][4][4];
#pragma unroll
        for (int m = 0; m < 2; m++)
#pragma unroll
            for (int ns = 0; ns < 4; ns++)
#pragma unroll
                for (int k = 0; k < 4; k++) acc[m][ns][k] = 0;

#pragma unroll
        for (int t = 0; t < 9; t++) {
            const int ky = t / 3, kx = t - 3 * (t / 3);
            unsigned af[2][4], bf[2][4];
            unsigned ao = abase + ((unsigned)(ky * 130 + kx) << 5);
            ldm4(af[0], actS + swz(ao));
            ldm4(af[1], actS + swz(ao + 512));
            unsigned bo = bbase + ((unsigned)t << 10);
            ldm4(bf[0], wS + swz(bo));
            ldm4(bf[1], wS + swz(bo + 512));
#pragma unroll
            for (int m = 0; m < 2; m++) {
                mma_s8(acc[m][0], af[m], bf[0][0], bf[0][1]);
                mma_s8(acc[m][1], af[m], bf[0][2], bf[0][3]);
                mma_s8(acc[m][2], af[m], bf[1][0], bf[1][1]);
                mma_s8(acc[m][3], af[m], bf[1][2], bf[1][3]);
            }
        }

        if (MODE == 0) {
#pragma unroll
            for (int m = 0; m < 2; m++)
#pragma unroll
                for (int ns = 0; ns < 4; ns++)
#pragma unroll
                    for (int k = 0; k < 4; k++) {
                        int a = acc[m][ns][k];
                        mret = max(mret, a < 0 ? -a : a);
                    }
        } else {
            int y = y0 + row;
#pragma unroll
            for (int m = 0; m < 2; m++)
#pragma unroll
                for (int ns = 0; ns < 4; ns++) {
                    int x0p = xbase + m * 16 + g;
                    int co0 = ns * 8 + tig * 2;
                    float* base0 = out + (((n * 32 + co0) * 128 + y) * 128);
                    float* base1 = base0 + 128 * 128;
                    base0[x0p] = quantize_one(acc[m][ns][0], shift, eff);
                    base1[x0p] = quantize_one(acc[m][ns][1], shift, eff);
                    base0[x0p + 8] = quantize_one(acc[m][ns][2], shift, eff);
                    base1[x0p + 8] = quantize_one(acc[m][ns][3], shift, eff);
                }
        }
    }
    return mret;
}

__global__ void __launch_bounds__(256, 2) k_fused(
    const int* __restrict__ act, const int* __restrict__ expin,
    const int* __restrict__ w, const int* __restrict__ wexp,
    float* __restrict__ out, int out_size) {
    __shared__ __align__(128) signed char s_act[4 * 130 * 32];
    __shared__ __align__(128) signed char s_w[9 * 32 * 32];

    int tid = threadIdx.x;
    int bl = blockIdx.x;

    // ---- Phase 1: NCHW int32 -> NHWC int8 (strided chunks, unroll-2 MLP) ----
    {
        int c = bl * 256 + tid;
#pragma unroll 2
        for (int it = 0; it < 14; it++) {
            if (c < NB * HH * WW * 2) {
                int half = c & 1;
                int p = c >> 1;
                int x = p & (WW - 1);
                int y = (p >> 7) & (HH - 1);
                int n = p >> 14;
                const int* src =
                    act + ((size_t)(n * CI + half * 16) * HH + y) * WW + x;
                unsigned vv[4];
#pragma unroll
                for (int j = 0; j < 4; j++) {
                    unsigned v = 0;
#pragma unroll
                    for (int bb = 0; bb < 4; bb++) {
                        unsigned cc =
                            (unsigned)src[(size_t)(j * 4 + bb) * HH * WW] & 0xFFu;
                        v |= cc << (8 * bb);
                    }
                    vv[j] = v;
                }
                *(uint4*)(g_act_nhwc + ((size_t)p << 5) + (half << 4)) =
                    make_uint4(vv[0], vv[1], vv[2], vv[3]);
            }
            c += GRID * 256;
        }
    }
    // block 0: pack weights + reset g_max (read only after gbar)
    if (bl == 0) {
        if (tid == 0) g_max = 0;
        for (int i = tid; i < CO * 9 * 8; i += 256) {
            int ciw = i & 7;
            int t = (i >> 3) % 9;
            int co = i / 72;
            int kh = t / 3, kw = t - kh * 3;
            unsigned v = 0;
#pragma unroll
            for (int j = 0; j < 4; j++) {
                int ci = ciw * 4 + j;
                unsigned b = (unsigned)(w[((co * CI + ci) * 3 + kh) * 3 + kw]) & 0xFFu;
                v |= b << (8 * j);
            }
            g_wpack[i] = v;
        }
    }
    gbar(&g_c1);

    // fill s_w (swizzled); first __syncthreads inside conv_pass publishes it
    for (int i = tid; i < 9 * 32 * 2; i += 256) {
        int h = i & 1;
        int co = (i >> 1) & 31;
        int t = i >> 6;
        unsigned off = ((unsigned)(t * 32 + co) << 5) + (h << 4);
        *(uint4*)(s_w + swz(off)) = ((const uint4*)g_wpack)[(co * 9 + t) * 2 + h];
    }

    // ---- Phase 2: conv, global |max| ----
    int mloc = conv_pass<0>(s_act, s_w, 0, 0, out);
    mloc = __reduce_max_sync(0xffffffffu, mloc);
    if ((tid & 31) == 0) atomicMax(&g_max, mloc);
    gbar(&g_c2);

    // ---- Phase 3: recompute conv, quantize, store ----
    int gmax = *(volatile int*)&g_max;
    int bw = gmax ? (32 - __clz(gmax - 1)) : 0;  // exact ceil(log2)
    int shift = bw - 7;
    int eff = shift > 1 ? shift : 2;
    conv_pass<1>(s_act, s_w, shift, eff, out);

    if (bl == 0 && tid == 0) {
        int inc = shift > 1 ? shift : (shift == 1 ? 2 : 0);
        int e = expin[0] + wexp[0] + inc;
        out[out_size - 1] = (float)(signed char)e;
    }

    // ---- last block resets barrier counters for the next graph replay ----
    __syncthreads();
    if (tid == 0) {
        __threadfence();
        unsigned old = atomicAdd(&g_c3, 1u);
        if (old == GRID - 1) {
            atomicExch(&g_c1, 0u);
            atomicExch(&g_c2, 0u);
            atomicExch(&g_c3, 0u);
        }
    }
}

extern "C" void kernel_launch(void* const* d_in, const int* in_sizes, int n_in,
                              void* d_out, int out_size) {
    const int* act = (const int*)d_in[0];
    const int* expin = (const int*)d_in[1];
    const int* w = (const int*)d_in[2];
    const int* wexp = (const int*)d_in[3];
    float* out = (float*)d_out;

    k_fused<<<GRID, 256>>>(act, expin, w, wexp, out, out_size);
}